// round 4
// baseline (speedup 1.0000x reference)
#include <cuda_runtime.h>
#include <math.h>

#define NB   4
#define NC   64
#define FSZ  65536            // F*S
#define CFS  4194304          // C*F*S
#define TPIX 64               // pixels per tile
#define PAD  72               // smem row stride (72 mod 32 == 8 -> conflict free)
#define EPSV 1e-5

// ---------------- scratch (no allocs allowed) ----------------
__device__ double g_acc[16];                 // per batch: {sx, sxx, sy, syy}
__device__ float  g_p[NB * NC];              // post-GLU channel sums
__device__ float  g_s[NB * NC];              // SE gate
__device__ float  g_u[(size_t)NB * CFS];     // post-GLU activations (67 MB)

// ---------------- helpers ----------------
__device__ __forceinline__ unsigned f2tf(float f) {
    unsigned u;
    asm("cvt.rna.tf32.f32 %0, %1;" : "=r"(u) : "f"(f));
    return u;
}
__device__ __forceinline__ void mma8(float acc[4], const unsigned a[4],
                                     unsigned b0, unsigned b1) {
    asm volatile(
        "mma.sync.aligned.m16n8k8.row.col.f32.tf32.tf32.f32 "
        "{%0,%1,%2,%3},{%4,%5,%6,%7},{%8,%9},{%0,%1,%2,%3};\n"
        : "+f"(acc[0]), "+f"(acc[1]), "+f"(acc[2]), "+f"(acc[3])
        : "r"(a[0]), "r"(a[1]), "r"(a[2]), "r"(a[3]), "r"(b0), "r"(b1));
}
__device__ __forceinline__ float sigm(float v) { return 1.f / (1.f + __expf(-v)); }

// ---------------- K0: zero accumulators ----------------
__global__ void k_zero() {
    int t = threadIdx.x;
    if (t < 16) g_acc[t] = 0.0;
    g_p[t] = 0.f;
}

// ---------------- K1: LN1 stats ----------------
__global__ __launch_bounds__(256) void k_stats1(const float* __restrict__ x) {
    int bat = blockIdx.x >> 9;
    int chunk = blockIdx.x & 511;
    size_t base = (size_t)bat * CFS + (size_t)chunk * 8192;
    float s = 0.f, ss = 0.f;
#pragma unroll
    for (int it = 0; it < 8; ++it) {
        float4 v = *(const float4*)(x + base + (size_t)(threadIdx.x + 256 * it) * 4);
        s  += (v.x + v.y) + (v.z + v.w);
        ss += (v.x * v.x + v.y * v.y) + (v.z * v.z + v.w * v.w);
    }
#pragma unroll
    for (int o = 16; o; o >>= 1) {
        s  += __shfl_xor_sync(0xffffffffu, s,  o);
        ss += __shfl_xor_sync(0xffffffffu, ss, o);
    }
    __shared__ float red[16];
    int w = threadIdx.x >> 5, lane = threadIdx.x & 31;
    if (!lane) { red[w] = s; red[8 + w] = ss; }
    __syncthreads();
    if (threadIdx.x == 0) {
        float S = 0.f, SS = 0.f;
#pragma unroll
        for (int i = 0; i < 8; ++i) { S += red[i]; SS += red[8 + i]; }
        atomicAdd(&g_acc[bat * 4 + 0], (double)S);
        atomicAdd(&g_acc[bat * 4 + 1], (double)SS);
    }
}

// ---------------- K2: LN1 -> GEMM1 -> dw affine -> GLU -> u, accumulate p ----------------
__global__ __launch_bounds__(256) void k_br1(
    const float* __restrict__ x,  const float* __restrict__ lnw,
    const float* __restrict__ lnb, const float* __restrict__ W1,
    const float* __restrict__ pb1, const float* __restrict__ dww,
    const float* __restrict__ dwb) {
    __shared__ float sm[NC * PAD];
    __shared__ float st[2];
    int tid = threadIdx.x, w = tid >> 5, lane = tid & 31;
    int bat = blockIdx.x >> 10;
    int tile = blockIdx.x & 1023;
    size_t base  = (size_t)bat * CFS + (size_t)tile * TPIX;  // batched tensors
    size_t pbase = (size_t)tile * TPIX;                      // LN params: NO batch dim!
    if (tid == 0) {
        double m = g_acc[bat * 4 + 0] * (1.0 / (double)CFS);
        double v = g_acc[bat * 4 + 1] * (1.0 / (double)CFS) - m * m;
        st[0] = (float)m;
        st[1] = (float)(1.0 / sqrt(v + EPSV));
    }
    __syncthreads();
    float m1 = st[0], r1 = st[1];
#pragma unroll
    for (int it = 0; it < 4; ++it) {
        int e = (tid + 256 * it) * 4;
        int row = e >> 6, col = e & 63;
        size_t g  = base  + (size_t)row * FSZ + col;
        size_t gp = pbase + (size_t)row * FSZ + col;
        float4 xv = *(const float4*)(x + g);
        float4 wv = *(const float4*)(lnw + gp);
        float4 bv = *(const float4*)(lnb + gp);
        float4 o;
        o.x = __uint_as_float(f2tf(fmaf((xv.x - m1) * r1, wv.x, bv.x)));
        o.y = __uint_as_float(f2tf(fmaf((xv.y - m1) * r1, wv.y, bv.y)));
        o.z = __uint_as_float(f2tf(fmaf((xv.z - m1) * r1, wv.z, bv.z)));
        o.w = __uint_as_float(f2tf(fmaf((xv.w - m1) * r1, wv.w, bv.w)));
        *(float4*)(sm + row * PAD + col) = o;
    }
    __syncthreads();
    // A fragments: warp w owns a-channels [8w,8w+8) (mma rows 0-7) and gate channels +64 (rows 8-15)
    int ra = 8 * w + (lane >> 2), rg = ra + 64, kc = lane & 3;
    unsigned A[8][4];
#pragma unroll
    for (int kt = 0; kt < 8; ++kt) {
        int k0 = kt * 8 + kc;
        A[kt][0] = f2tf(W1[ra * 64 + k0]);
        A[kt][1] = f2tf(W1[rg * 64 + k0]);
        A[kt][2] = f2tf(W1[ra * 64 + k0 + 4]);
        A[kt][3] = f2tf(W1[rg * 64 + k0 + 4]);
    }
    float acc[8][4];
#pragma unroll
    for (int i = 0; i < 8; ++i)
#pragma unroll
        for (int j = 0; j < 4; ++j) acc[i][j] = 0.f;
#pragma unroll
    for (int nt = 0; nt < 8; ++nt) {
        int n0 = nt * 8 + (lane >> 2);
#pragma unroll
        for (int kt = 0; kt < 8; ++kt) {
            int kr = kt * 8 + kc;
            unsigned bb0 = __float_as_uint(sm[kr * PAD + n0]);
            unsigned bb1 = __float_as_uint(sm[(kr + 4) * PAD + n0]);
            mma8(acc[nt], A[kt], bb0, bb1);
        }
    }
    // epilogue: +b1, dw affine, GLU; a/g pair is in-register
    float b1a = pb1[ra], b1g = pb1[rg];
    float dwa = dww[ra], dba = dwb[ra], dwg = dww[rg], dbg = dwb[rg];
    float ur[16];
    float psum = 0.f;
#pragma unroll
    for (int nt = 0; nt < 8; ++nt) {
        float a0 = fmaf(acc[nt][0] + b1a, dwa, dba);
        float a1 = fmaf(acc[nt][1] + b1a, dwa, dba);
        float g0 = fmaf(acc[nt][2] + b1g, dwg, dbg);
        float g1 = fmaf(acc[nt][3] + b1g, dwg, dbg);
        float u0 = a0 * sigm(g0);
        float u1 = a1 * sigm(g1);
        ur[nt * 2] = u0; ur[nt * 2 + 1] = u1;
        psum += u0 + u1;
    }
    psum += __shfl_xor_sync(0xffffffffu, psum, 1);
    psum += __shfl_xor_sync(0xffffffffu, psum, 2);
    if ((lane & 3) == 0) atomicAdd(&g_p[bat * 64 + ra], psum);
    __syncthreads();
#pragma unroll
    for (int nt = 0; nt < 8; ++nt) {
        int c0 = nt * 8 + (lane & 3) * 2;
        sm[ra * PAD + c0]     = ur[nt * 2];
        sm[ra * PAD + c0 + 1] = ur[nt * 2 + 1];
    }
    __syncthreads();
#pragma unroll
    for (int it = 0; it < 4; ++it) {
        int e = (tid + 256 * it) * 4;
        int row = e >> 6, col = e & 63;
        *(float4*)(g_u + base + (size_t)row * FSZ + col) = *(float4*)(sm + row * PAD + col);
    }
}

// ---------------- K3: SE gate ----------------
__global__ void k_attn(const float* __restrict__ aw1, const float* __restrict__ ab1,
                       const float* __restrict__ aw2, const float* __restrict__ ab2) {
    __shared__ float pm[256], t1[256];
    int tid = threadIdx.x;
    int bat = tid >> 6, c = tid & 63;
    pm[tid] = g_p[tid] * (1.f / 65536.f);
    __syncthreads();
    float a = ab1[c];
#pragma unroll 8
    for (int j = 0; j < 64; ++j) a = fmaf(pm[bat * 64 + j], aw1[c * 64 + j], a);
    t1[tid] = fmaxf(a, 0.f);
    __syncthreads();
    float a2 = ab2[c];
#pragma unroll 8
    for (int j = 0; j < 64; ++j) a2 = fmaf(t1[bat * 64 + j], aw2[c * 64 + j], a2);
    g_s[tid] = sigm(a2);
}

// ---------------- K4: y = W2@(u*s) + b2 + x ; LN2 stats ----------------
__global__ __launch_bounds__(256) void k_y(
    const float* __restrict__ x, const float* __restrict__ W2,
    const float* __restrict__ pb2, float* __restrict__ yo) {
    __shared__ float smu[NC * PAD];
    __shared__ float smx[NC * PAD];
    __shared__ float ssg[64];
    __shared__ float red[16];
    int tid = threadIdx.x, w = tid >> 5, lane = tid & 31;
    int bat = blockIdx.x >> 10;
    int tile = blockIdx.x & 1023;
    size_t base = (size_t)bat * CFS + (size_t)tile * TPIX;
    if (tid < 64) ssg[tid] = g_s[bat * 64 + tid];
    __syncthreads();
#pragma unroll
    for (int it = 0; it < 4; ++it) {
        int e = (tid + 256 * it) * 4;
        int row = e >> 6, col = e & 63;
        size_t g = base + (size_t)row * FSZ + col;
        float4 uv = *(const float4*)(g_u + g);
        float4 xv = *(const float4*)(x + g);
        float sg = ssg[row];
        float4 o;
        o.x = __uint_as_float(f2tf(uv.x * sg));
        o.y = __uint_as_float(f2tf(uv.y * sg));
        o.z = __uint_as_float(f2tf(uv.z * sg));
        o.w = __uint_as_float(f2tf(uv.w * sg));
        *(float4*)(smu + row * PAD + col) = o;
        *(float4*)(smx + row * PAD + col) = xv;
    }
    __syncthreads();
    int mt = w & 3, half = w >> 2;
    int r0 = mt * 16 + (lane >> 2), r1r = r0 + 8, kc = lane & 3;
    unsigned A[8][4];
#pragma unroll
    for (int kt = 0; kt < 8; ++kt) {
        int k0 = kt * 8 + kc;
        A[kt][0] = f2tf(W2[r0  * 64 + k0]);
        A[kt][1] = f2tf(W2[r1r * 64 + k0]);
        A[kt][2] = f2tf(W2[r0  * 64 + k0 + 4]);
        A[kt][3] = f2tf(W2[r1r * 64 + k0 + 4]);
    }
    float acc[4][4];
#pragma unroll
    for (int i = 0; i < 4; ++i)
#pragma unroll
        for (int j = 0; j < 4; ++j) acc[i][j] = 0.f;
#pragma unroll
    for (int nt = 0; nt < 4; ++nt) {
        int n0 = half * 32 + nt * 8 + (lane >> 2);
#pragma unroll
        for (int kt = 0; kt < 8; ++kt) {
            int kr = kt * 8 + kc;
            unsigned bb0 = __float_as_uint(smu[kr * PAD + n0]);
            unsigned bb1 = __float_as_uint(smu[(kr + 4) * PAD + n0]);
            mma8(acc[nt], A[kt], bb0, bb1);
        }
    }
    float bc0 = pb2[r0], bc1 = pb2[r1r];
    float yr[16];
    float sy = 0.f, syy = 0.f;
#pragma unroll
    for (int nt = 0; nt < 4; ++nt) {
        int c0 = half * 32 + nt * 8 + (lane & 3) * 2;
        float y00 = acc[nt][0] + bc0 + smx[r0  * PAD + c0];
        float y01 = acc[nt][1] + bc0 + smx[r0  * PAD + c0 + 1];
        float y10 = acc[nt][2] + bc1 + smx[r1r * PAD + c0];
        float y11 = acc[nt][3] + bc1 + smx[r1r * PAD + c0 + 1];
        yr[nt * 4 + 0] = y00; yr[nt * 4 + 1] = y01;
        yr[nt * 4 + 2] = y10; yr[nt * 4 + 3] = y11;
        sy  += (y00 + y01) + (y10 + y11);
        syy += (y00 * y00 + y01 * y01) + (y10 * y10 + y11 * y11);
    }
    __syncthreads();   // all warps done reading smu
#pragma unroll
    for (int nt = 0; nt < 4; ++nt) {
        int c0 = half * 32 + nt * 8 + (lane & 3) * 2;
        smu[r0  * PAD + c0]     = yr[nt * 4 + 0];
        smu[r0  * PAD + c0 + 1] = yr[nt * 4 + 1];
        smu[r1r * PAD + c0]     = yr[nt * 4 + 2];
        smu[r1r * PAD + c0 + 1] = yr[nt * 4 + 3];
    }
#pragma unroll
    for (int o = 16; o; o >>= 1) {
        sy  += __shfl_xor_sync(0xffffffffu, sy,  o);
        syy += __shfl_xor_sync(0xffffffffu, syy, o);
    }
    if (!lane) { red[w] = sy; red[8 + w] = syy; }
    __syncthreads();
    if (tid == 0) {
        float S = 0.f, SS = 0.f;
#pragma unroll
        for (int i = 0; i < 8; ++i) { S += red[i]; SS += red[8 + i]; }
        atomicAdd(&g_acc[bat * 4 + 2], (double)S);
        atomicAdd(&g_acc[bat * 4 + 3], (double)SS);
    }
#pragma unroll
    for (int it = 0; it < 4; ++it) {
        int e = (tid + 256 * it) * 4;
        int row = e >> 6, col = e & 63;
        *(float4*)(yo + base + (size_t)row * FSZ + col) = *(float4*)(smu + row * PAD + col);
    }
}

// ---------------- K5: LN2 -> GEMM3 -> GLU -> GEMM4 -> +y ----------------
__global__ __launch_bounds__(256) void k_br2(
    const float* __restrict__ lnw, const float* __restrict__ lnb,
    const float* __restrict__ W3,  const float* __restrict__ pb3,
    const float* __restrict__ W4,  const float* __restrict__ pb4,
    float* __restrict__ io) {
    __shared__ float smy[NC * PAD];
    __shared__ float smb[NC * PAD];
    __shared__ float st[2];
    int tid = threadIdx.x, w = tid >> 5, lane = tid & 31;
    int bat = blockIdx.x >> 10;
    int tile = blockIdx.x & 1023;
    size_t base  = (size_t)bat * CFS + (size_t)tile * TPIX;
    size_t pbase = (size_t)tile * TPIX;                      // LN params: NO batch dim!
    if (tid == 0) {
        double m = g_acc[bat * 4 + 2] * (1.0 / (double)CFS);
        double v = g_acc[bat * 4 + 3] * (1.0 / (double)CFS) - m * m;
        st[0] = (float)m;
        st[1] = (float)(1.0 / sqrt(v + EPSV));
    }
    __syncthreads();
    float m2 = st[0], r2 = st[1];
#pragma unroll
    for (int it = 0; it < 4; ++it) {
        int e = (tid + 256 * it) * 4;
        int row = e >> 6, col = e & 63;
        size_t g  = base  + (size_t)row * FSZ + col;
        size_t gp = pbase + (size_t)row * FSZ + col;
        float4 yv = *(const float4*)(io + g);
        float4 wv = *(const float4*)(lnw + gp);
        float4 bv = *(const float4*)(lnb + gp);
        *(float4*)(smy + row * PAD + col) = yv;
        float4 o;
        o.x = __uint_as_float(f2tf(fmaf((yv.x - m2) * r2, wv.x, bv.x)));
        o.y = __uint_as_float(f2tf(fmaf((yv.y - m2) * r2, wv.y, bv.y)));
        o.z = __uint_as_float(f2tf(fmaf((yv.z - m2) * r2, wv.z, bv.z)));
        o.w = __uint_as_float(f2tf(fmaf((yv.w - m2) * r2, wv.w, bv.w)));
        *(float4*)(smb + row * PAD + col) = o;
    }
    __syncthreads();
    // GEMM3 (128x64) with GLU row pairing
    int ra = 8 * w + (lane >> 2), rg = ra + 64, kc = lane & 3;
    {
        unsigned A[8][4];
#pragma unroll
        for (int kt = 0; kt < 8; ++kt) {
            int k0 = kt * 8 + kc;
            A[kt][0] = f2tf(W3[ra * 64 + k0]);
            A[kt][1] = f2tf(W3[rg * 64 + k0]);
            A[kt][2] = f2tf(W3[ra * 64 + k0 + 4]);
            A[kt][3] = f2tf(W3[rg * 64 + k0 + 4]);
        }
        float acc[8][4];
#pragma unroll
        for (int i = 0; i < 8; ++i)
#pragma unroll
            for (int j = 0; j < 4; ++j) acc[i][j] = 0.f;
#pragma unroll
        for (int nt = 0; nt < 8; ++nt) {
            int n0 = nt * 8 + (lane >> 2);
#pragma unroll
            for (int kt = 0; kt < 8; ++kt) {
                int kr = kt * 8 + kc;
                unsigned bb0 = __float_as_uint(smb[kr * PAD + n0]);
                unsigned bb1 = __float_as_uint(smb[(kr + 4) * PAD + n0]);
                mma8(acc[nt], A[kt], bb0, bb1);
            }
        }
        float b3a = pb3[ra], b3g = pb3[rg];
        float ur[16];
#pragma unroll
        for (int nt = 0; nt < 8; ++nt) {
            float a0 = acc[nt][0] + b3a;
            float a1 = acc[nt][1] + b3a;
            float g0 = acc[nt][2] + b3g;
            float g1 = acc[nt][3] + b3g;
            ur[nt * 2]     = a0 * sigm(g0);
            ur[nt * 2 + 1] = a1 * sigm(g1);
        }
        __syncthreads();  // done reading ln2 from smb
#pragma unroll
        for (int nt = 0; nt < 8; ++nt) {
            int c0 = nt * 8 + (lane & 3) * 2;
            smb[ra * PAD + c0]     = __uint_as_float(f2tf(ur[nt * 2]));
            smb[ra * PAD + c0 + 1] = __uint_as_float(f2tf(ur[nt * 2 + 1]));
        }
        __syncthreads();
    }
    // GEMM4 (64x64): out = W4@u2 + b4 + y
    int mt = w & 3, half = w >> 2;
    int r0 = mt * 16 + (lane >> 2), r1r = r0 + 8;
    unsigned A2[8][4];
#pragma unroll
    for (int kt = 0; kt < 8; ++kt) {
        int k0 = kt * 8 + kc;
        A2[kt][0] = f2tf(W4[r0  * 64 + k0]);
        A2[kt][1] = f2tf(W4[r1r * 64 + k0]);
        A2[kt][2] = f2tf(W4[r0  * 64 + k0 + 4]);
        A2[kt][3] = f2tf(W4[r1r * 64 + k0 + 4]);
    }
    float ac2[4][4];
#pragma unroll
    for (int i = 0; i < 4; ++i)
#pragma unroll
        for (int j = 0; j < 4; ++j) ac2[i][j] = 0.f;
#pragma unroll
    for (int nt = 0; nt < 4; ++nt) {
        int n0 = half * 32 + nt * 8 + (lane >> 2);
#pragma unroll
        for (int kt = 0; kt < 8; ++kt) {
            int kr = kt * 8 + kc;
            unsigned bb0 = __float_as_uint(smb[kr * PAD + n0]);
            unsigned bb1 = __float_as_uint(smb[(kr + 4) * PAD + n0]);
            mma8(ac2[nt], A2[kt], bb0, bb1);
        }
    }
    float b40 = pb4[r0], b41 = pb4[r1r];
    float outr[16];
#pragma unroll
    for (int nt = 0; nt < 4; ++nt) {
        int c0 = half * 32 + nt * 8 + (lane & 3) * 2;
        outr[nt * 4 + 0] = ac2[nt][0] + b40 + smy[r0  * PAD + c0];
        outr[nt * 4 + 1] = ac2[nt][1] + b40 + smy[r0  * PAD + c0 + 1];
        outr[nt * 4 + 2] = ac2[nt][2] + b41 + smy[r1r * PAD + c0];
        outr[nt * 4 + 3] = ac2[nt][3] + b41 + smy[r1r * PAD + c0 + 1];
    }
    __syncthreads();  // done reading u2 from smb
#pragma unroll
    for (int nt = 0; nt < 4; ++nt) {
        int c0 = half * 32 + nt * 8 + (lane & 3) * 2;
        smb[r0  * PAD + c0]     = outr[nt * 4 + 0];
        smb[r0  * PAD + c0 + 1] = outr[nt * 4 + 1];
        smb[r1r * PAD + c0]     = outr[nt * 4 + 2];
        smb[r1r * PAD + c0 + 1] = outr[nt * 4 + 3];
    }
    __syncthreads();
#pragma unroll
    for (int it = 0; it < 4; ++it) {
        int e = (tid + 256 * it) * 4;
        int row = e >> 6, col = e & 63;
        *(float4*)(io + base + (size_t)row * FSZ + col) = *(float4*)(smb + row * PAD + col);
    }
}

// ---------------- launch ----------------
extern "C" void kernel_launch(void* const* d_in, const int* in_sizes, int n_in,
                              void* d_out, int out_size) {
    const float* x   = (const float*)d_in[0];
    const float* l1w = (const float*)d_in[1];
    const float* l1b = (const float*)d_in[2];
    const float* l2w = (const float*)d_in[3];
    const float* l2b = (const float*)d_in[4];
    const float* W1  = (const float*)d_in[5];
    const float* b1  = (const float*)d_in[6];
    const float* dww = (const float*)d_in[7];
    const float* dwb = (const float*)d_in[8];
    const float* aw1 = (const float*)d_in[9];
    const float* ab1 = (const float*)d_in[10];
    const float* aw2 = (const float*)d_in[11];
    const float* ab2 = (const float*)d_in[12];
    const float* W2  = (const float*)d_in[13];
    const float* b2  = (const float*)d_in[14];
    const float* W3  = (const float*)d_in[15];
    const float* b3  = (const float*)d_in[16];
    const float* W4  = (const float*)d_in[17];
    const float* b4  = (const float*)d_in[18];
    float* out = (float*)d_out;

    k_zero<<<1, 256>>>();
    k_stats1<<<NB * 512, 256>>>(x);
    k_br1<<<NB * 1024, 256>>>(x, l1w, l1b, W1, b1, dww, dwb);
    k_attn<<<1, 256>>>(aw1, ab1, aw2, ab2);
    k_y<<<NB * 1024, 256>>>(x, W2, b2, out);
    k_br2<<<NB * 1024, 256>>>(l2w, l2b, W3, b3, W4, b4, out);
}